// round 11
// baseline (speedup 1.0000x reference)
#include <cuda_runtime.h>
#include <cuda_fp16.h>
#include <cstdint>

#define N_VERT 500000
#define C 64
#define FE 9
#define NF 64
#define EPS 1e-5f

#define STATS_BLOCKS 2048
#define STATS_THREADS 256
#define TILE_M 256
#define N_TILES ((N_VERT + TILE_M - 1) / TILE_M)   // 1954
#define GEMM_GRID 148                              // 1 CTA per SM, 8 warps

// ---------------------------------------------------------------------------
// Device scratch (allocation-free)
// ---------------------------------------------------------------------------
__device__ float  g_partial[STATS_BLOCKS * 128];
__device__ float  g_scale[C];
__device__ float  g_shift[C];
__device__ __half g_xh[(size_t)N_VERT * C];     // fp16(relu(gn(lv)))  64 MB
// W fragments (fp16), mma.sync B lane order.
// chunk = (f*4 + ks)*8 + nb ; index t = chunk*32 + lane ; uint2 per lane
__device__ uint4 g_wf[FE * 4 * 8 * 32 / 2];     // 4608 uint4 = 73728 B

// SMEM layout (dynamic, 128B-aligned base), per CTA
#define OFF_B    0
#define OFF_A    73728                        // per-warp rings follow B
#define WARP_RING 16384                       // 4 stages x 32 rows x 128 B
#define A_STAGE  4096
#define SMEM_BYTES (73728 + 8 * 16384 + 128)  // 204928 (1 CTA/SM)

__device__ __forceinline__ uint32_t swz(uint32_t off) { return off ^ ((off >> 3) & 0x70); }

__device__ __forceinline__ uint32_t smem_u32(const void* p) {
    uint32_t a;
    asm("{ .reg .u64 t; cvta.to.shared.u64 t, %1; cvt.u32.u64 %0, t; }"
        : "=r"(a) : "l"(p));
    return a;
}
__device__ __forceinline__ void cp_async16(uint32_t dst, const void* src) {
    asm volatile("cp.async.cg.shared.global [%0], [%1], 16;"
                 :: "r"(dst), "l"(src) : "memory");
}
__device__ __forceinline__ void cp_commit() {
    asm volatile("cp.async.commit_group;" ::: "memory");
}
template <int N>
__device__ __forceinline__ void cp_wait() {
    asm volatile("cp.async.wait_group %0;" :: "n"(N) : "memory");
}
__device__ __forceinline__ void ldmatrix_x4(uint32_t* r, uint32_t addr) {
    asm volatile("ldmatrix.sync.aligned.m8n8.x4.shared.b16 {%0,%1,%2,%3}, [%4];"
                 : "=r"(r[0]), "=r"(r[1]), "=r"(r[2]), "=r"(r[3]) : "r"(addr));
}
__device__ __forceinline__ void mma16816(float* d, const uint32_t* a, uint32_t b0, uint32_t b1) {
    asm volatile(
        "mma.sync.aligned.m16n8k16.row.col.f32.f16.f16.f32 "
        "{%0,%1,%2,%3}, {%4,%5,%6,%7}, {%8,%9}, {%0,%1,%2,%3};"
        : "+f"(d[0]), "+f"(d[1]), "+f"(d[2]), "+f"(d[3])
        : "r"(a[0]), "r"(a[1]), "r"(a[2]), "r"(a[3]), "r"(b0), "r"(b1));
}

// ---------------------------------------------------------------------------
// Kernel 1: per-channel partial sums (deterministic)
// ---------------------------------------------------------------------------
__global__ void __launch_bounds__(STATS_THREADS)
stats_kernel(const float* __restrict__ lv) {
    const int tid = threadIdx.x;
    const long long total4 = (long long)N_VERT * C / 4;
    const long long stride = (long long)gridDim.x * blockDim.x;
    long long i = (long long)blockIdx.x * blockDim.x + tid;

    float sx = 0.f, sy = 0.f, sz = 0.f, sw = 0.f;
    float qx = 0.f, qy = 0.f, qz = 0.f, qw = 0.f;
    const float4* lv4 = (const float4*)lv;
    for (; i < total4; i += stride) {
        float4 v = lv4[i];
        sx += v.x; sy += v.y; sz += v.z; sw += v.w;
        qx += v.x * v.x; qy += v.y * v.y; qz += v.z * v.z; qw += v.w * v.w;
    }
    sx += __shfl_xor_sync(0xffffffffu, sx, 16);
    sy += __shfl_xor_sync(0xffffffffu, sy, 16);
    sz += __shfl_xor_sync(0xffffffffu, sz, 16);
    sw += __shfl_xor_sync(0xffffffffu, sw, 16);
    qx += __shfl_xor_sync(0xffffffffu, qx, 16);
    qy += __shfl_xor_sync(0xffffffffu, qy, 16);
    qz += __shfl_xor_sync(0xffffffffu, qz, 16);
    qw += __shfl_xor_sync(0xffffffffu, qw, 16);

    __shared__ float shs[8][64];
    __shared__ float shq[8][64];
    const int wid = tid >> 5, lane = tid & 31;
    if (lane < 16) {
        const int c0 = lane * 4;
        shs[wid][c0 + 0] = sx; shs[wid][c0 + 1] = sy;
        shs[wid][c0 + 2] = sz; shs[wid][c0 + 3] = sw;
        shq[wid][c0 + 0] = qx; shq[wid][c0 + 1] = qy;
        shq[wid][c0 + 2] = qz; shq[wid][c0 + 3] = qw;
    }
    __syncthreads();
    if (tid < 64) {
        float s = 0.f, q = 0.f;
        #pragma unroll
        for (int w = 0; w < 8; w++) { s += shs[w][tid]; q += shq[w][tid]; }
        g_partial[blockIdx.x * 128 + tid]      = s;
        g_partial[blockIdx.x * 128 + 64 + tid] = q;
    }
}

// ---------------------------------------------------------------------------
// Kernel 2: finalize -> scale/shift
// ---------------------------------------------------------------------------
__global__ void finalize_kernel(const float* __restrict__ gamma,
                                const float* __restrict__ beta) {
    const int c = threadIdx.x;
    float s = 0.f, q = 0.f;
    for (int b = 0; b < STATS_BLOCKS; b++) {
        s += g_partial[b * 128 + c];
        q += g_partial[b * 128 + 64 + c];
    }
    __shared__ float shs[64], shq[64];
    shs[c] = s; shq[c] = q;
    __syncthreads();
    const int g = c >> 1;
    const float gs = shs[2 * g] + shs[2 * g + 1];
    const float gq = shq[2 * g] + shq[2 * g + 1];
    const float inv = 1.0f / (2.0f * (float)N_VERT);
    const float mean = gs * inv;
    const float var  = gq * inv - mean * mean;
    const float rstd = rsqrtf(var + EPS);
    const float sc = rstd * gamma[c];
    g_scale[c] = sc;
    g_shift[c] = beta[c] - mean * sc;
}

// ---------------------------------------------------------------------------
// Kernel 3: xh = fp16(relu(gn(lv)))
// ---------------------------------------------------------------------------
__global__ void __launch_bounds__(256)
convert_kernel(const float* __restrict__ lv) {
    const long long total4 = (long long)N_VERT * C / 4;
    const long long stride = (long long)gridDim.x * blockDim.x;
    long long i = (long long)blockIdx.x * blockDim.x + threadIdx.x;
    const int c0 = (int)((i & 15) * 4);
    const float4 sc = *(const float4*)&g_scale[c0];
    const float4 sh = *(const float4*)&g_shift[c0];
    const float4* src = (const float4*)lv;
    uint2* dst = (uint2*)g_xh;
    for (; i < total4; i += stride) {
        float4 v = src[i];
        v.x = fmaxf(fmaf(v.x, sc.x, sh.x), 0.f);
        v.y = fmaxf(fmaf(v.y, sc.y, sh.y), 0.f);
        v.z = fmaxf(fmaf(v.z, sc.z, sh.z), 0.f);
        v.w = fmaxf(fmaf(v.w, sc.w, sh.w), 0.f);
        union { uint2 u; __half2 h[2]; } pk;
        pk.h[0] = __floats2half2_rn(v.x, v.y);
        pk.h[1] = __floats2half2_rn(v.z, v.w);
        dst[i] = pk.u;
    }
}

// ---------------------------------------------------------------------------
// Kernel 4: W -> fragment-ordered fp16
// ---------------------------------------------------------------------------
__global__ void wfrag_kernel(const float* __restrict__ W) {
    const int t = blockIdx.x * blockDim.x + threadIdx.x;
    if (t >= FE * 4 * 8 * 32) return;
    const int lane  = t & 31;
    const int chunk = t >> 5;
    const int nb = chunk & 7;
    const int ks = (chunk >> 3) & 3;
    const int f  = chunk >> 5;
    const int n  = nb * 8 + (lane >> 2);
    const int k0 = ks * 16 + 2 * (lane & 3);

    float w0 = W[(long long)(f * C + k0 + 0) * NF + n];
    float w1 = W[(long long)(f * C + k0 + 1) * NF + n];
    float w2 = W[(long long)(f * C + k0 + 8) * NF + n];
    float w3 = W[(long long)(f * C + k0 + 9) * NF + n];

    union { uint2 u; __half2 h[2]; } pk;
    pk.h[0] = __halves2half2(__float2half_rn(w0), __float2half_rn(w1));
    pk.h[1] = __halves2half2(__float2half_rn(w2), __float2half_rn(w3));
    ((uint2*)g_wf)[t] = pk.u;
}

// ---------------------------------------------------------------------------
// Kernel 5: persistent HMMA GEMM, warp-independent pipelines, M=32 per warp.
// Each warp owns a 32-row strip x full N=64 (2 MMAs per B-fragment load);
// per-warp 4-stage cp.async ring; no block barriers in the main loop.
// ---------------------------------------------------------------------------
__global__ void __launch_bounds__(256)
gemm_mma_kernel(const int* __restrict__ nidx, const float* __restrict__ bias,
                float* __restrict__ out) {
    extern __shared__ char dsm[];
    char* SB = (char*)(((uintptr_t)dsm + 127) & ~(uintptr_t)127);
    const uint32_t sb = smem_u32(SB);

    const int tid = threadIdx.x;
    const int wid = tid >> 5;
    const int lid = tid & 31;
    const int qc = lid & 3;
    const int gr = lid >> 2;

    // --- stage W fragments into SMEM (72 KB, once) ---
    {
        uint4* bsm = (uint4*)(SB + OFF_B);
        for (int i = tid; i < 4608; i += 256) bsm[i] = g_wf[i];
    }
    __syncthreads();

    float2 bb[8];
    #pragma unroll
    for (int nb = 0; nb < 8; nb++)
        bb[nb] = *(const float2*)(bias + nb * 8 + qc * 2);

    // gather mapping: each lane owns one local row (0..31), full 128 B
    const uint32_t fill_off = (uint32_t)(lid * 128);
    const uint32_t ring = sb + OFF_A + wid * WARP_RING;

    // ldmatrix lane address components
    const int lrow8 = (lid & 7) + ((lid & 8) ? 8 : 0);
    const uint32_t lcol = (lid & 16) ? 16u : 0u;

    int t = blockIdx.x;
    if (t >= N_TILES) return;

    // --- warp prologue: idx for first tile, fill taps 0..2 ---
    int idxCur[FE], idxNxt[FE];
    {
        int grow = t * TILE_M + wid * 32 + lid;
        if (grow >= N_VERT) grow = N_VERT - 1;
        #pragma unroll
        for (int f = 0; f < FE; f++) idxCur[f] = nidx[(long long)grow * FE + f];
    }
    #pragma unroll
    for (int f = 0; f < 3; f++) {
        const char* src = (const char*)g_xh + (size_t)idxCur[f] * 128;
        const uint32_t d = ring + (uint32_t)f * A_STAGE;
        #pragma unroll
        for (int j = 0; j < 8; j++)
            cp_async16(d + swz(fill_off + j * 16), src + j * 16);
        cp_commit();
    }

    int st = 0;  // ring stage of current tap

    for (; t < N_TILES; t += GEMM_GRID) {
        const bool last = (t + GEMM_GRID >= N_TILES);
        const int strip = t * TILE_M + wid * 32;

        // prefetch next tile's indices (consumed starting at slot f==6)
        if (!last) {
            int grow2 = (t + GEMM_GRID) * TILE_M + wid * 32 + lid;
            if (grow2 >= N_VERT) grow2 = N_VERT - 1;
            #pragma unroll
            for (int f = 0; f < FE; f++) idxNxt[f] = nidx[(long long)grow2 * FE + f];
        }

        float acc[2][8][4];
        #pragma unroll
        for (int mt = 0; mt < 2; mt++)
            #pragma unroll
            for (int nb = 0; nb < 8; nb++)
                #pragma unroll
                for (int j = 0; j < 4; j++) acc[mt][nb][j] = 0.f;

        #pragma unroll
        for (int f = 0; f < FE; f++) {
            if (!last || f < 7) cp_wait<2>();
            else if (f == 7)    cp_wait<1>();
            else                cp_wait<0>();
            __syncwarp();

            // fill slot: tap f+3 of this tile, or tap f-6 of next tile
            {
                const int gf = f + 3;
                int fidx = -1;
                if (gf < FE)    fidx = idxCur[gf];
                else if (!last) fidx = idxNxt[gf - FE];
                if (fidx >= 0) {
                    const char* src = (const char*)g_xh + (size_t)fidx * 128;
                    const uint32_t d = ring + (uint32_t)((st + 3) & 3) * A_STAGE;
                    #pragma unroll
                    for (int j = 0; j < 8; j++)
                        cp_async16(d + swz(fill_off + j * 16), src + j * 16);
                    cp_commit();
                }
            }

            // compute tap f from stage st
            const uint32_t ab = ring + (uint32_t)st * A_STAGE;
            #pragma unroll
            for (int ks = 0; ks < 4; ks++) {
                uint32_t a[2][4];
                #pragma unroll
                for (int mt = 0; mt < 2; mt++)
                    ldmatrix_x4(a[mt], ab + swz((uint32_t)((mt * 16 + lrow8) * 128 + ks * 32 + lcol)));
                #pragma unroll
                for (int nb = 0; nb < 8; nb++) {
                    const int chunk = (f * 4 + ks) * 8 + nb;
                    const uint2 bf = *(const uint2*)(SB + OFF_B + (size_t)(chunk * 32 + lid) * 8);
                    #pragma unroll
                    for (int mt = 0; mt < 2; mt++)
                        mma16816(acc[mt][nb], a[mt], bf.x, bf.y);
                }
            }
            st = (st + 1) & 3;
        }

        // --- epilogue: bias + direct STG (warp-private rows) ---
        #pragma unroll
        for (int mt = 0; mt < 2; mt++) {
            const int r0 = strip + mt * 16 + gr;
            #pragma unroll
            for (int nb = 0; nb < 8; nb++) {
                const int col = nb * 8 + qc * 2;
                if (r0 < N_VERT) {
                    float2 v; v.x = acc[mt][nb][0] + bb[nb].x;
                              v.y = acc[mt][nb][1] + bb[nb].y;
                    *(float2*)(out + (long long)r0 * NF + col) = v;
                }
                if (r0 + 8 < N_VERT) {
                    float2 v; v.x = acc[mt][nb][2] + bb[nb].x;
                              v.y = acc[mt][nb][3] + bb[nb].y;
                    *(float2*)(out + (long long)(r0 + 8) * NF + col) = v;
                }
            }
        }

        // rotate idx buffers
        #pragma unroll
        for (int f = 0; f < FE; f++) idxCur[f] = idxNxt[f];
    }
}

// ---------------------------------------------------------------------------
// Launch
// ---------------------------------------------------------------------------
extern "C" void kernel_launch(void* const* d_in, const int* in_sizes, int n_in,
                              void* d_out, int out_size) {
    const float* lv        = (const float*)d_in[0];
    const int*   neigh_idx = (const int*)d_in[1];
    const float* gamma     = (const float*)d_in[2];
    const float* beta      = (const float*)d_in[3];
    const float* weight    = (const float*)d_in[4];
    const float* conv_bias = (const float*)d_in[5];
    float* out = (float*)d_out;

    cudaFuncSetAttribute(gemm_mma_kernel,
                         cudaFuncAttributeMaxDynamicSharedMemorySize, SMEM_BYTES);

    stats_kernel<<<STATS_BLOCKS, STATS_THREADS>>>(lv);
    finalize_kernel<<<1, 64>>>(gamma, beta);
    convert_kernel<<<4096, 256>>>(lv);
    wfrag_kernel<<<(FE * 4 * 8 * 32 + 255) / 256, 256>>>(weight);
    gemm_mma_kernel<<<GEMM_GRID, 256, SMEM_BYTES>>>(neigh_idx, conv_bias, out);
}

// round 12
// speedup vs baseline: 1.0788x; 1.0788x over previous
#include <cuda_runtime.h>
#include <cuda_fp16.h>
#include <cstdint>

#define N_VERT 500000
#define C 64
#define FE 9
#define NF 64
#define EPS 1e-5f

#define STATS_BLOCKS 2048
#define STATS_THREADS 256
#define TILE_M 64
#define N_TILES ((N_VERT + TILE_M - 1) / TILE_M)   // 7813
#define GEMM_GRID (2 * 148)                        // 2 CTAs per SM

// ---------------------------------------------------------------------------
// Device scratch (allocation-free)
// ---------------------------------------------------------------------------
__device__ float  g_partial[STATS_BLOCKS * 128];
__device__ float  g_scale[C];
__device__ float  g_shift[C];
__device__ __half g_xh[(size_t)N_VERT * C];     // fp16(relu(gn(lv)))  64 MB
// W fragments (fp16), mma.sync B lane order.
// chunk = (f*4 + ks)*8 + nb ; index t = chunk*32 + lane ; uint2 per lane
__device__ uint4 g_wf[FE * 4 * 8 * 32 / 2];     // 4608 uint4 = 73728 B

// SMEM layout (dynamic, 128B-aligned base), per CTA
#define OFF_B    0
#define OFF_A    73728                       // per-warp rings follow B
#define WARP_RING 8192                       // 4 stages x 16 rows x 128 B
#define A_STAGE  2048
#define SMEM_BYTES (73728 + 4 * 8192 + 128)  // 106624 -> 2 CTAs/SM

__device__ __forceinline__ uint32_t swz(uint32_t off) { return off ^ ((off >> 3) & 0x70); }

__device__ __forceinline__ uint32_t smem_u32(const void* p) {
    uint32_t a;
    asm("{ .reg .u64 t; cvta.to.shared.u64 t, %1; cvt.u32.u64 %0, t; }"
        : "=r"(a) : "l"(p));
    return a;
}
__device__ __forceinline__ void cp_async16(uint32_t dst, const void* src) {
    asm volatile("cp.async.cg.shared.global [%0], [%1], 16;"
                 :: "r"(dst), "l"(src) : "memory");
}
__device__ __forceinline__ void cp_commit() {
    asm volatile("cp.async.commit_group;" ::: "memory");
}
template <int N>
__device__ __forceinline__ void cp_wait() {
    asm volatile("cp.async.wait_group %0;" :: "n"(N) : "memory");
}
__device__ __forceinline__ void ldmatrix_x4(uint32_t* r, uint32_t addr) {
    asm volatile("ldmatrix.sync.aligned.m8n8.x4.shared.b16 {%0,%1,%2,%3}, [%4];"
                 : "=r"(r[0]), "=r"(r[1]), "=r"(r[2]), "=r"(r[3]) : "r"(addr));
}
__device__ __forceinline__ void mma16816(float* d, const uint32_t* a, uint32_t b0, uint32_t b1) {
    asm volatile(
        "mma.sync.aligned.m16n8k16.row.col.f32.f16.f16.f32 "
        "{%0,%1,%2,%3}, {%4,%5,%6,%7}, {%8,%9}, {%0,%1,%2,%3};"
        : "+f"(d[0]), "+f"(d[1]), "+f"(d[2]), "+f"(d[3])
        : "r"(a[0]), "r"(a[1]), "r"(a[2]), "r"(a[3]), "r"(b0), "r"(b1));
}

// ---------------------------------------------------------------------------
// Kernel 1: per-channel partial sums (deterministic)
// ---------------------------------------------------------------------------
__global__ void __launch_bounds__(STATS_THREADS)
stats_kernel(const float* __restrict__ lv) {
    const int tid = threadIdx.x;
    const long long total4 = (long long)N_VERT * C / 4;
    const long long stride = (long long)gridDim.x * blockDim.x;
    long long i = (long long)blockIdx.x * blockDim.x + tid;

    float sx = 0.f, sy = 0.f, sz = 0.f, sw = 0.f;
    float qx = 0.f, qy = 0.f, qz = 0.f, qw = 0.f;
    const float4* lv4 = (const float4*)lv;
    for (; i < total4; i += stride) {
        float4 v = lv4[i];
        sx += v.x; sy += v.y; sz += v.z; sw += v.w;
        qx += v.x * v.x; qy += v.y * v.y; qz += v.z * v.z; qw += v.w * v.w;
    }
    sx += __shfl_xor_sync(0xffffffffu, sx, 16);
    sy += __shfl_xor_sync(0xffffffffu, sy, 16);
    sz += __shfl_xor_sync(0xffffffffu, sz, 16);
    sw += __shfl_xor_sync(0xffffffffu, sw, 16);
    qx += __shfl_xor_sync(0xffffffffu, qx, 16);
    qy += __shfl_xor_sync(0xffffffffu, qy, 16);
    qz += __shfl_xor_sync(0xffffffffu, qz, 16);
    qw += __shfl_xor_sync(0xffffffffu, qw, 16);

    __shared__ float shs[8][64];
    __shared__ float shq[8][64];
    const int wid = tid >> 5, lane = tid & 31;
    if (lane < 16) {
        const int c0 = lane * 4;
        shs[wid][c0 + 0] = sx; shs[wid][c0 + 1] = sy;
        shs[wid][c0 + 2] = sz; shs[wid][c0 + 3] = sw;
        shq[wid][c0 + 0] = qx; shq[wid][c0 + 1] = qy;
        shq[wid][c0 + 2] = qz; shq[wid][c0 + 3] = qw;
    }
    __syncthreads();
    if (tid < 64) {
        float s = 0.f, q = 0.f;
        #pragma unroll
        for (int w = 0; w < 8; w++) { s += shs[w][tid]; q += shq[w][tid]; }
        g_partial[blockIdx.x * 128 + tid]      = s;
        g_partial[blockIdx.x * 128 + 64 + tid] = q;
    }
}

// ---------------------------------------------------------------------------
// Kernel 2 (fused): finalize stats -> scale/shift  +  W fragment pack.
// grid = 36 x 256 (covers 9216 wfrag elements). Block 0 threads 0..63 also
// run finalize, barrier-free (group of 2 channels reduced via shfl_xor 1).
// ---------------------------------------------------------------------------
__global__ void __launch_bounds__(256)
finwfrag_kernel(const float* __restrict__ W,
                const float* __restrict__ gamma,
                const float* __restrict__ beta) {
    const int t = blockIdx.x * blockDim.x + threadIdx.x;

    // finalize (block 0, warps 0-1 fully active)
    if (blockIdx.x == 0 && threadIdx.x < 64) {
        const int c = threadIdx.x;
        float s = 0.f, q = 0.f;
        for (int b = 0; b < STATS_BLOCKS; b++) {
            s += g_partial[b * 128 + c];
            q += g_partial[b * 128 + 64 + c];
        }
        // group = 2 adjacent channels; partner lane c^1 is in-warp
        const float gs = s + __shfl_xor_sync(0xffffffffu, s, 1);
        const float gq = q + __shfl_xor_sync(0xffffffffu, q, 1);
        const float inv = 1.0f / (2.0f * (float)N_VERT);
        const float mean = gs * inv;
        const float var  = gq * inv - mean * mean;
        const float rstd = rsqrtf(var + EPS);
        const float sc = rstd * gamma[c];
        g_scale[c] = sc;
        g_shift[c] = beta[c] - mean * sc;
    }

    // wfrag
    if (t < FE * 4 * 8 * 32) {
        const int lane  = t & 31;
        const int chunk = t >> 5;
        const int nb = chunk & 7;
        const int ks = (chunk >> 3) & 3;
        const int f  = chunk >> 5;
        const int n  = nb * 8 + (lane >> 2);
        const int k0 = ks * 16 + 2 * (lane & 3);

        float w0 = W[(long long)(f * C + k0 + 0) * NF + n];
        float w1 = W[(long long)(f * C + k0 + 1) * NF + n];
        float w2 = W[(long long)(f * C + k0 + 8) * NF + n];
        float w3 = W[(long long)(f * C + k0 + 9) * NF + n];

        union { uint2 u; __half2 h[2]; } pk;
        pk.h[0] = __halves2half2(__float2half_rn(w0), __float2half_rn(w1));
        pk.h[1] = __halves2half2(__float2half_rn(w2), __float2half_rn(w3));
        ((uint2*)g_wf)[t] = pk.u;
    }
}

// ---------------------------------------------------------------------------
// Kernel 3: xh = fp16(relu(gn(lv)))
// ---------------------------------------------------------------------------
__global__ void __launch_bounds__(256)
convert_kernel(const float* __restrict__ lv) {
    const long long total4 = (long long)N_VERT * C / 4;
    const long long stride = (long long)gridDim.x * blockDim.x;
    long long i = (long long)blockIdx.x * blockDim.x + threadIdx.x;
    const int c0 = (int)((i & 15) * 4);
    const float4 sc = *(const float4*)&g_scale[c0];
    const float4 sh = *(const float4*)&g_shift[c0];
    const float4* src = (const float4*)lv;
    uint2* dst = (uint2*)g_xh;
    for (; i < total4; i += stride) {
        float4 v = src[i];
        v.x = fmaxf(fmaf(v.x, sc.x, sh.x), 0.f);
        v.y = fmaxf(fmaf(v.y, sc.y, sh.y), 0.f);
        v.z = fmaxf(fmaf(v.z, sc.z, sh.z), 0.f);
        v.w = fmaxf(fmaf(v.w, sc.w, sh.w), 0.f);
        union { uint2 u; __half2 h[2]; } pk;
        pk.h[0] = __floats2half2_rn(v.x, v.y);
        pk.h[1] = __floats2half2_rn(v.z, v.w);
        dst[i] = pk.u;
    }
}

// ---------------------------------------------------------------------------
// Kernel 4: persistent HMMA GEMM (R8 winner config).
// Each warp owns a 16-row strip x full N=64; per-warp 4-stage cp.async ring;
// no block barriers in the main loop; cross-tile pipelining.
// ---------------------------------------------------------------------------
__global__ void __launch_bounds__(128)
gemm_mma_kernel(const int* __restrict__ nidx, const float* __restrict__ bias,
                float* __restrict__ out) {
    extern __shared__ char dsm[];
    char* SB = (char*)(((uintptr_t)dsm + 127) & ~(uintptr_t)127);
    const uint32_t sb = smem_u32(SB);

    const int tid = threadIdx.x;
    const int wid = tid >> 5;
    const int lid = tid & 31;
    const int qc = lid & 3;
    const int gr = lid >> 2;

    // --- stage W fragments into SMEM (72 KB, once) ---
    {
        uint4* bsm = (uint4*)(SB + OFF_B);
        for (int i = tid; i < 4608; i += 128) bsm[i] = g_wf[i];
    }
    __syncthreads();

    float2 bb[8];
    #pragma unroll
    for (int nb = 0; nb < 8; nb++)
        bb[nb] = *(const float2*)(bias + nb * 8 + qc * 2);

    // gather mapping: lane covers local row rl = lid>>1 (0..15), 64B half hf
    const int rl = lid >> 1;
    const int hf = lid & 1;
    const uint32_t fill_off = (uint32_t)(rl * 128 + hf * 64);
    const uint32_t ring = sb + OFF_A + wid * WARP_RING;

    // ldmatrix lane address components
    const int lrow8 = (lid & 7) + ((lid & 8) ? 8 : 0);
    const uint32_t lcol = (lid & 16) ? 16u : 0u;

    int t = blockIdx.x;
    if (t >= N_TILES) return;

    // --- warp prologue: idx for first tile, fill taps 0..2 ---
    int idxCur[FE], idxNxt[FE];
    {
        int grow = t * TILE_M + wid * 16 + rl;
        if (grow >= N_VERT) grow = N_VERT - 1;
        #pragma unroll
        for (int f = 0; f < FE; f++) idxCur[f] = nidx[(long long)grow * FE + f];
    }
    #pragma unroll
    for (int f = 0; f < 3; f++) {
        const char* src = (const char*)g_xh + (size_t)idxCur[f] * 128 + hf * 64;
        const uint32_t d = ring + (uint32_t)f * A_STAGE;
        #pragma unroll
        for (int j = 0; j < 4; j++)
            cp_async16(d + swz(fill_off + j * 16), src + j * 16);
        cp_commit();
    }

    int st = 0;  // ring stage of current tap

    for (; t < N_TILES; t += GEMM_GRID) {
        const bool last = (t + GEMM_GRID >= N_TILES);
        const int m0 = t * TILE_M;
        const int strip = m0 + wid * 16;

        // prefetch next tile's indices (used from slot f==6)
        if (!last) {
            int grow2 = (t + GEMM_GRID) * TILE_M + wid * 16 + rl;
            if (grow2 >= N_VERT) grow2 = N_VERT - 1;
            #pragma unroll
            for (int f = 0; f < FE; f++) idxNxt[f] = nidx[(long long)grow2 * FE + f];
        }

        float acc[8][4];
        #pragma unroll
        for (int nb = 0; nb < 8; nb++)
            #pragma unroll
            for (int j = 0; j < 4; j++) acc[nb][j] = 0.f;

        #pragma unroll
        for (int f = 0; f < FE; f++) {
            if (!last || f < 7) cp_wait<2>();
            else if (f == 7)    cp_wait<1>();
            else                cp_wait<0>();
            __syncwarp();

            // fill slot: tap f+3 of this tile, or tap f-6 of next tile
            {
                const int gf = f + 3;
                int fidx = -1;
                if (gf < FE)        fidx = idxCur[gf];
                else if (!last)     fidx = idxNxt[gf - FE];
                if (fidx >= 0) {
                    const char* src = (const char*)g_xh + (size_t)fidx * 128 + hf * 64;
                    const uint32_t d = ring + (uint32_t)((st + 3) & 3) * A_STAGE;
                    #pragma unroll
                    for (int j = 0; j < 4; j++)
                        cp_async16(d + swz(fill_off + j * 16), src + j * 16);
                    cp_commit();
                }
            }

            // compute tap f from stage st
            const uint32_t ab = ring + (uint32_t)st * A_STAGE;
            #pragma unroll
            for (int ks = 0; ks < 4; ks++) {
                uint32_t a[4];
                ldmatrix_x4(a, ab + swz((uint32_t)(lrow8 * 128 + ks * 32 + lcol)));
                #pragma unroll
                for (int nb = 0; nb < 8; nb++) {
                    const int chunk = (f * 4 + ks) * 8 + nb;
                    const uint2 bf = *(const uint2*)(SB + OFF_B + (size_t)(chunk * 32 + lid) * 8);
                    mma16816(acc[nb], a, bf.x, bf.y);
                }
            }
            st = (st + 1) & 3;
        }

        // --- epilogue: bias + direct STG (warp-private rows) ---
        {
            const int r0 = strip + gr;
            #pragma unroll
            for (int nb = 0; nb < 8; nb++) {
                const int col = nb * 8 + qc * 2;
                if (r0 < N_VERT) {
                    float2 v; v.x = acc[nb][0] + bb[nb].x;
                              v.y = acc[nb][1] + bb[nb].y;
                    *(float2*)(out + (long long)r0 * NF + col) = v;
                }
                if (r0 + 8 < N_VERT) {
                    float2 v; v.x = acc[nb][2] + bb[nb].x;
                              v.y = acc[nb][3] + bb[nb].y;
                    *(float2*)(out + (long long)(r0 + 8) * NF + col) = v;
                }
            }
        }

        // rotate idx buffers
        #pragma unroll
        for (int f = 0; f < FE; f++) idxCur[f] = idxNxt[f];
    }
}

// ---------------------------------------------------------------------------
// Launch: stats(0), fin+wfrag(1), convert(2), gemm(3)
//   (gemm now sits at launch index 3, where ncu's capture window lands)
// ---------------------------------------------------------------------------
extern "C" void kernel_launch(void* const* d_in, const int* in_sizes, int n_in,
                              void* d_out, int out_size) {
    const float* lv        = (const float*)d_in[0];
    const int*   neigh_idx = (const int*)d_in[1];
    const float* gamma     = (const float*)d_in[2];
    const float* beta      = (const float*)d_in[3];
    const float* weight    = (const float*)d_in[4];
    const float* conv_bias = (const float*)d_in[5];
    float* out = (float*)d_out;

    cudaFuncSetAttribute(gemm_mma_kernel,
                         cudaFuncAttributeMaxDynamicSharedMemorySize, SMEM_BYTES);

    stats_kernel<<<STATS_BLOCKS, STATS_THREADS>>>(lv);
    finwfrag_kernel<<<36, 256>>>(weight, gamma, beta);
    convert_kernel<<<4096, 256>>>(lv);
    gemm_mma_kernel<<<GEMM_GRID, 128, SMEM_BYTES>>>(neigh_idx, conv_bias, out);
}

// round 14
// speedup vs baseline: 1.2722x; 1.1793x over previous
#include <cuda_runtime.h>
#include <cuda_fp16.h>
#include <cstdint>

#define N_VERT 500000
#define C 64
#define FE 9
#define NF 64
#define EPS 1e-5f

#define STATS_BLOCKS 2048
#define STATS_THREADS 256
#define TILE_M 192
#define N_TILES ((N_VERT + TILE_M - 1) / TILE_M)   // 2605
#define GEMM_GRID 148                              // 1 CTA/SM, 12 warps
#define GEMM_THREADS 384

// ---------------------------------------------------------------------------
// Device scratch (allocation-free)
// ---------------------------------------------------------------------------
__device__ float  g_partial[STATS_BLOCKS * 128];
__device__ float  g_scale[C];
__device__ float  g_shift[C];
__device__ __half g_xh[(size_t)N_VERT * C];     // fp16(relu(gn(lv)))  64 MB
// W fragments (fp16), mma.sync B lane order, ks-PAIRED:
// chunk = (f*2 + kp)*8 + nb ; per lane uint4 = {ks=2kp:(k0,k1),(k0+8,k1+8),
//                                               ks=2kp+1: same}
__device__ uint4 g_wf[FE * 2 * 8 * 32];         // 4608 uint4 = 73728 B

// SMEM layout (dynamic, 128B-aligned base), per CTA
#define OFF_B    0
#define OFF_A    73728                        // per-warp rings follow B
#define WARP_RING 8192                        // 4 stages x 16 rows x 128 B
#define A_STAGE  2048
#define SMEM_BYTES (73728 + 12 * 8192 + 128)  // 172160 (1 CTA/SM)

__device__ __forceinline__ uint32_t swz(uint32_t off) { return off ^ ((off >> 3) & 0x70); }

__device__ __forceinline__ uint32_t smem_u32(const void* p) {
    uint32_t a;
    asm("{ .reg .u64 t; cvta.to.shared.u64 t, %1; cvt.u32.u64 %0, t; }"
        : "=r"(a) : "l"(p));
    return a;
}
__device__ __forceinline__ void cp_async16(uint32_t dst, const void* src) {
    asm volatile("cp.async.cg.shared.global [%0], [%1], 16;"
                 :: "r"(dst), "l"(src) : "memory");
}
__device__ __forceinline__ void cp_commit() {
    asm volatile("cp.async.commit_group;" ::: "memory");
}
template <int N>
__device__ __forceinline__ void cp_wait() {
    asm volatile("cp.async.wait_group %0;" :: "n"(N) : "memory");
}
__device__ __forceinline__ void ldmatrix_x4(uint32_t* r, uint32_t addr) {
    asm volatile("ldmatrix.sync.aligned.m8n8.x4.shared.b16 {%0,%1,%2,%3}, [%4];"
                 : "=r"(r[0]), "=r"(r[1]), "=r"(r[2]), "=r"(r[3]) : "r"(addr));
}
__device__ __forceinline__ void mma16816(float* d, const uint32_t* a, uint32_t b0, uint32_t b1) {
    asm volatile(
        "mma.sync.aligned.m16n8k16.row.col.f32.f16.f16.f32 "
        "{%0,%1,%2,%3}, {%4,%5,%6,%7}, {%8,%9}, {%0,%1,%2,%3};"
        : "+f"(d[0]), "+f"(d[1]), "+f"(d[2]), "+f"(d[3])
        : "r"(a[0]), "r"(a[1]), "r"(a[2]), "r"(a[3]), "r"(b0), "r"(b1));
}

// ---------------------------------------------------------------------------
// Kernel 1: per-channel partial sums (deterministic)
// ---------------------------------------------------------------------------
__global__ void __launch_bounds__(STATS_THREADS)
stats_kernel(const float* __restrict__ lv) {
    const int tid = threadIdx.x;
    const long long total4 = (long long)N_VERT * C / 4;
    const long long stride = (long long)gridDim.x * blockDim.x;
    long long i = (long long)blockIdx.x * blockDim.x + tid;

    float sx = 0.f, sy = 0.f, sz = 0.f, sw = 0.f;
    float qx = 0.f, qy = 0.f, qz = 0.f, qw = 0.f;
    const float4* lv4 = (const float4*)lv;
    for (; i < total4; i += stride) {
        float4 v = lv4[i];
        sx += v.x; sy += v.y; sz += v.z; sw += v.w;
        qx += v.x * v.x; qy += v.y * v.y; qz += v.z * v.z; qw += v.w * v.w;
    }
    sx += __shfl_xor_sync(0xffffffffu, sx, 16);
    sy += __shfl_xor_sync(0xffffffffu, sy, 16);
    sz += __shfl_xor_sync(0xffffffffu, sz, 16);
    sw += __shfl_xor_sync(0xffffffffu, sw, 16);
    qx += __shfl_xor_sync(0xffffffffu, qx, 16);
    qy += __shfl_xor_sync(0xffffffffu, qy, 16);
    qz += __shfl_xor_sync(0xffffffffu, qz, 16);
    qw += __shfl_xor_sync(0xffffffffu, qw, 16);

    __shared__ float shs[8][64];
    __shared__ float shq[8][64];
    const int wid = tid >> 5, lane = tid & 31;
    if (lane < 16) {
        const int c0 = lane * 4;
        shs[wid][c0 + 0] = sx; shs[wid][c0 + 1] = sy;
        shs[wid][c0 + 2] = sz; shs[wid][c0 + 3] = sw;
        shq[wid][c0 + 0] = qx; shq[wid][c0 + 1] = qy;
        shq[wid][c0 + 2] = qz; shq[wid][c0 + 3] = qw;
    }
    __syncthreads();
    if (tid < 64) {
        float s = 0.f, q = 0.f;
        #pragma unroll
        for (int w = 0; w < 8; w++) { s += shs[w][tid]; q += shq[w][tid]; }
        g_partial[blockIdx.x * 128 + tid]      = s;
        g_partial[blockIdx.x * 128 + 64 + tid] = q;
    }
}

// ---------------------------------------------------------------------------
// Kernel 2 (fused): finalize stats -> scale/shift  +  W fragment pack.
// ---------------------------------------------------------------------------
__global__ void __launch_bounds__(256)
finwfrag_kernel(const float* __restrict__ W,
                const float* __restrict__ gamma,
                const float* __restrict__ beta) {
    const int t = blockIdx.x * blockDim.x + threadIdx.x;

    // finalize (block 0, warps 0-1)
    if (blockIdx.x == 0 && threadIdx.x < 64) {
        const int c = threadIdx.x;
        float s = 0.f, q = 0.f;
        for (int b = 0; b < STATS_BLOCKS; b++) {
            s += g_partial[b * 128 + c];
            q += g_partial[b * 128 + 64 + c];
        }
        const float gs = s + __shfl_xor_sync(0xffffffffu, s, 1);
        const float gq = q + __shfl_xor_sync(0xffffffffu, q, 1);
        const float inv = 1.0f / (2.0f * (float)N_VERT);
        const float mean = gs * inv;
        const float var  = gq * inv - mean * mean;
        const float rstd = rsqrtf(var + EPS);
        const float sc = rstd * gamma[c];
        g_scale[c] = sc;
        g_shift[c] = beta[c] - mean * sc;
    }

    // wfrag: one thread per uint4 (ks pair)
    if (t < FE * 2 * 8 * 32) {
        const int lane  = t & 31;
        const int chunk = t >> 5;
        const int nb = chunk & 7;
        const int kp = (chunk >> 3) & 1;
        const int f  = chunk >> 4;
        const int n  = nb * 8 + (lane >> 2);

        union { uint4 u; __half2 h[4]; } pk;
        #pragma unroll
        for (int h = 0; h < 2; h++) {
            const int ks = 2 * kp + h;
            const int k0 = ks * 16 + 2 * (lane & 3);
            float w0 = W[(long long)(f * C + k0 + 0) * NF + n];
            float w1 = W[(long long)(f * C + k0 + 1) * NF + n];
            float w2 = W[(long long)(f * C + k0 + 8) * NF + n];
            float w3 = W[(long long)(f * C + k0 + 9) * NF + n];
            pk.h[2 * h + 0] = __halves2half2(__float2half_rn(w0), __float2half_rn(w1));
            pk.h[2 * h + 1] = __halves2half2(__float2half_rn(w2), __float2half_rn(w3));
        }
        g_wf[t] = pk.u;
    }
}

// ---------------------------------------------------------------------------
// Kernel 3: xh = fp16(relu(gn(lv)))
// ---------------------------------------------------------------------------
__global__ void __launch_bounds__(256)
convert_kernel(const float* __restrict__ lv) {
    const long long total4 = (long long)N_VERT * C / 4;
    const long long stride = (long long)gridDim.x * blockDim.x;
    long long i = (long long)blockIdx.x * blockDim.x + threadIdx.x;
    const int c0 = (int)((i & 15) * 4);
    const float4 sc = *(const float4*)&g_scale[c0];
    const float4 sh = *(const float4*)&g_shift[c0];
    const float4* src = (const float4*)lv;
    uint2* dst = (uint2*)g_xh;
    for (; i < total4; i += stride) {
        float4 v = src[i];
        v.x = fmaxf(fmaf(v.x, sc.x, sh.x), 0.f);
        v.y = fmaxf(fmaf(v.y, sc.y, sh.y), 0.f);
        v.z = fmaxf(fmaf(v.z, sc.z, sh.z), 0.f);
        v.w = fmaxf(fmaf(v.w, sc.w, sh.w), 0.f);
        union { uint2 u; __half2 h[2]; } pk;
        pk.h[0] = __floats2half2_rn(v.x, v.y);
        pk.h[1] = __floats2half2_rn(v.z, v.w);
        dst[i] = pk.u;
    }
}

// ---------------------------------------------------------------------------
// Kernel 4: persistent HMMA GEMM. 12 warps/CTA, 1 CTA/SM, M=16/warp.
// Warp-independent 4-stage cp.async rings; no block barriers in main loop;
// B via LDS.128 ks-pairs.
// ---------------------------------------------------------------------------
__global__ void __launch_bounds__(GEMM_THREADS)
gemm_mma_kernel(const int* __restrict__ nidx, const float* __restrict__ bias,
                float* __restrict__ out) {
    extern __shared__ char dsm[];
    char* SB = (char*)(((uintptr_t)dsm + 127) & ~(uintptr_t)127);
    const uint32_t sb = smem_u32(SB);

    const int tid = threadIdx.x;
    const int wid = tid >> 5;          // 0..11
    const int lid = tid & 31;
    const int qc = lid & 3;
    const int gr = lid >> 2;

    // --- stage W fragments into SMEM (72 KB, once) ---
    {
        uint4* bsm = (uint4*)(SB + OFF_B);
        for (int i = tid; i < 4608; i += GEMM_THREADS) bsm[i] = g_wf[i];
    }
    __syncthreads();

    float2 bb[8];
    #pragma unroll
    for (int nb = 0; nb < 8; nb++)
        bb[nb] = *(const float2*)(bias + nb * 8 + qc * 2);

    // gather mapping: lane covers local row rl = lid>>1 (0..15), 64B half hf
    const int rl = lid >> 1;
    const int hf = lid & 1;
    const uint32_t fill_off = (uint32_t)(rl * 128 + hf * 64);
    const uint32_t ring = sb + OFF_A + wid * WARP_RING;

    // ldmatrix lane address components
    const int lrow8 = (lid & 7) + ((lid & 8) ? 8 : 0);
    const uint32_t lcol = (lid & 16) ? 16u : 0u;

    int t = blockIdx.x;
    if (t >= N_TILES) return;

    // --- warp prologue: idx for first tile, fill taps 0..2 ---
    int idxCur[FE], idxNxt[FE];
    {
        int grow = t * TILE_M + wid * 16 + rl;
        if (grow >= N_VERT) grow = N_VERT - 1;
        #pragma unroll
        for (int f = 0; f < FE; f++) idxCur[f] = nidx[(long long)grow * FE + f];
    }
    #pragma unroll
    for (int f = 0; f < 3; f++) {
        const char* src = (const char*)g_xh + (size_t)idxCur[f] * 128 + hf * 64;
        const uint32_t d = ring + (uint32_t)f * A_STAGE;
        #pragma unroll
        for (int j = 0; j < 4; j++)
            cp_async16(d + swz(fill_off + j * 16), src + j * 16);
        cp_commit();
    }

    int st = 0;  // ring stage of current tap

    for (; t < N_TILES; t += GEMM_GRID) {
        const bool last = (t + GEMM_GRID >= N_TILES);
        const int strip = t * TILE_M + wid * 16;

        // prefetch next tile's indices (consumed from slot f==6)
        if (!last) {
            int grow2 = (t + GEMM_GRID) * TILE_M + wid * 16 + rl;
            if (grow2 >= N_VERT) grow2 = N_VERT - 1;
            #pragma unroll
            for (int f = 0; f < FE; f++) idxNxt[f] = nidx[(long long)grow2 * FE + f];
        }

        float acc[8][4];
        #pragma unroll
        for (int nb = 0; nb < 8; nb++)
            #pragma unroll
            for (int j = 0; j < 4; j++) acc[nb][j] = 0.f;

        #pragma unroll
        for (int f = 0; f < FE; f++) {
            if (!last || f < 7) cp_wait<2>();
            else if (f == 7)    cp_wait<1>();
            else                cp_wait<0>();
            __syncwarp();

            // fill slot: tap f+3 of this tile, or tap f-6 of next tile
            {
                const int gf = f + 3;
                int fidx = -1;
                if (gf < FE)    fidx = idxCur[gf];
                else if (!last) fidx = idxNxt[gf - FE];
                if (fidx >= 0) {
                    const char* src = (const char*)g_xh + (size_t)fidx * 128 + hf * 64;
                    const uint32_t d = ring + (uint32_t)((st + 3) & 3) * A_STAGE;
                    #pragma unroll
                    for (int j = 0; j < 4; j++)
                        cp_async16(d + swz(fill_off + j * 16), src + j * 16);
                    cp_commit();
                }
            }

            // compute tap f from stage st
            const uint32_t ab = ring + (uint32_t)st * A_STAGE;
            #pragma unroll
            for (int kp = 0; kp < 2; kp++) {
                uint32_t a0[4], a1[4];
                ldmatrix_x4(a0, ab + swz((uint32_t)(lrow8 * 128 + (2 * kp) * 32 + lcol)));
                ldmatrix_x4(a1, ab + swz((uint32_t)(lrow8 * 128 + (2 * kp + 1) * 32 + lcol)));
                #pragma unroll
                for (int nb = 0; nb < 8; nb++) {
                    const int chunk = (f * 2 + kp) * 8 + nb;
                    const uint4 bf = *(const uint4*)(SB + OFF_B + (size_t)(chunk * 32 + lid) * 16);
                    mma16816(acc[nb], a0, bf.x, bf.y);
                    mma16816(acc[nb], a1, bf.z, bf.w);
                }
            }
            st = (st + 1) & 3;
        }

        // --- epilogue: bias + direct STG (warp-private rows) ---
        {
            const int r0 = strip + gr;
            #pragma unroll
            for (int nb = 0; nb < 8; nb++) {
                const int col = nb * 8 + qc * 2;
                if (r0 < N_VERT) {
                    float2 v; v.x = acc[nb][0] + bb[nb].x;
                              v.y = acc[nb][1] + bb[nb].y;
                    *(float2*)(out + (long long)r0 * NF + col) = v;
                }
                if (r0 + 8 < N_VERT) {
                    float2 v; v.x = acc[nb][2] + bb[nb].x;
                              v.y = acc[nb][3] + bb[nb].y;
                    *(float2*)(out + (long long)(r0 + 8) * NF + col) = v;
                }
            }
        }

        // rotate idx buffers
        #pragma unroll
        for (int f = 0; f < FE; f++) idxCur[f] = idxNxt[f];
    }
}

// ---------------------------------------------------------------------------
// Launch: stats(0), fin+wfrag(1), convert(2), gemm(3)
// ---------------------------------------------------------------------------
extern "C" void kernel_launch(void* const* d_in, const int* in_sizes, int n_in,
                              void* d_out, int out_size) {
    const float* lv        = (const float*)d_in[0];
    const int*   neigh_idx = (const int*)d_in[1];
    const float* gamma     = (const float*)d_in[2];
    const float* beta      = (const float*)d_in[3];
    const float* weight    = (const float*)d_in[4];
    const float* conv_bias = (const float*)d_in[5];
    float* out = (float*)d_out;

    cudaFuncSetAttribute(gemm_mma_kernel,
                         cudaFuncAttributeMaxDynamicSharedMemorySize, SMEM_BYTES);

    stats_kernel<<<STATS_BLOCKS, STATS_THREADS>>>(lv);
    finwfrag_kernel<<<18, 256>>>(weight, gamma, beta);
    convert_kernel<<<4096, 256>>>(lv);
    gemm_mma_kernel<<<GEMM_GRID, GEMM_THREADS, SMEM_BYTES>>>(neigh_idx, conv_bias, out);
}